// round 3
// baseline (speedup 1.0000x reference)
#include <cuda_runtime.h>
#include <cstdint>

// ---------------- problem constants ----------------
#define T_SIZE 32768
#define TMASK  32767u
#define P1 2654435761u
#define P2 805459861u
#define MAXN (1 << 20)
#define BLK 256

// scratch: compacted active points (no cudaMalloc allowed)
__device__ float4 g_pts[MAXN];
__device__ int    g_count;

typedef unsigned long long u64;

// ---------------- packed f32x2 helpers (FFMA2) ----------------
__device__ __forceinline__ u64 pk2(float x, float y) {
    u64 r; asm("mov.b64 %0,{%1,%2};" : "=l"(r) : "f"(x), "f"(y)); return r;
}
__device__ __forceinline__ float2 up2(u64 v) {
    float2 f; asm("mov.b64 {%0,%1},%2;" : "=f"(f.x), "=f"(f.y) : "l"(v)); return f;
}
__device__ __forceinline__ u64 fma2(u64 a, u64 b, u64 c) {
    u64 d; asm("fma.rn.f32x2 %0,%1,%2,%3;" : "=l"(d) : "l"(a), "l"(b), "l"(c));
    return d;
}

// ---------------- kernel 1: mask + defaults + compaction ----------------
__global__ void k_mask_compact(const float* __restrict__ xyz,
                               const float* __restrict__ bmin,
                               const float* __restrict__ bmax,
                               float* __restrict__ out, int N)
{
    int i = blockIdx.x * blockDim.x + threadIdx.x;
    bool inb = false;
    float cx = 0.f, cy = 0.f, cz = 0.f;

    if (i < N) {
        float bx0 = bmin[0], by0 = bmin[1], bz0 = bmin[2];
        float bx1 = bmax[0], by1 = bmax[1], bz1 = bmax[2];
        float x = xyz[3 * i + 0];
        float y = xyz[3 * i + 1];
        float z = xyz[3 * i + 2];
        cx = (x - bx0) / (bx1 - bx0);
        cy = (y - by0) / (by1 - by0);
        cz = (z - bz0) / (bz1 - bz0);
        inb = (cx >= 0.f) & (cx <= 1.f) &
              (cy >= 0.f) & (cy <= 1.f) &
              (cz >= 0.f) & (cz <= 1.f);

        out[i] = inb ? 1.f : 0.f;
        float* dxyz = out + N;
        float* drot = out + (size_t)4 * N;
        dxyz[3 * i + 0] = 0.f;
        dxyz[3 * i + 1] = 0.f;
        dxyz[3 * i + 2] = 0.f;
        drot[4 * i + 0] = 1.f;
        drot[4 * i + 1] = 0.f;
        drot[4 * i + 2] = 0.f;
        drot[4 * i + 3] = 0.f;
    }

    unsigned m = __ballot_sync(0xffffffffu, inb);
    if (inb) {
        int lane = threadIdx.x & 31;
        int leader = __ffs(m) - 1;
        int base = 0;
        if (lane == leader) base = atomicAdd(&g_count, __popc(m));
        base = __shfl_sync(m, base, leader);
        int slot = base + __popc(m & ((1u << lane) - 1u));
        cx = fminf(fmaxf(cx, 0.f), 1.f);
        cy = fminf(fmaxf(cy, 0.f), 1.f);
        cz = fminf(fmaxf(cz, 0.f), 1.f);
        g_pts[slot] = make_float4(cx, cy, cz, __int_as_float(i));
    }
}

// ---------------- kernel 2: encode + MLP, packed f32x2 ----------------
// smem: [w0 16KB][w1 16KB][w2 2KB][act 32*BLK u64 = 64KB]  -> 100352 B
#define SMEM_BYTES (34816 + 32 * BLK * 8)

__global__ __launch_bounds__(BLK, 2)
void k_encode_mlp(const float* __restrict__ table,
                  const float* __restrict__ w0,
                  const float* __restrict__ w1,
                  const float* __restrict__ w2,
                  float* __restrict__ out, int N)
{
    extern __shared__ char smch[];
    float* sw0  = (float*)smch;        // 4096 floats
    float* sw1  = sw0 + 4096;          // 4096 floats
    float* sw2  = sw1 + 4096;          // 512 floats
    u64*   sact = (u64*)(sw2 + 512);   // 32 * BLK u64

    int tid = threadIdx.x;
    for (int k = tid; k < 4096 / 4; k += BLK)
        ((float4*)sw0)[k] = ((const float4*)w0)[k];
    for (int k = tid; k < 4096 / 4; k += BLK)
        ((float4*)sw1)[k] = ((const float4*)w1)[k];
    for (int k = tid; k < 512 / 4; k += BLK)
        ((float4*)sw2)[k] = ((const float4*)w2)[k];
    __syncthreads();

    int cnt = g_count;
    const float4* tbl = (const float4*)table;
    float* dxyz = out + N;
    float* drot = out + (size_t)4 * N;
    const ulonglong2* w0v = (const ulonglong2*)sw0;  // 16B = 2 packed f32x2
    const ulonglong2* w1v = (const ulonglong2*)sw1;
    const ulonglong2* w2v = (const ulonglong2*)sw2;

    for (int slot = blockIdx.x * BLK + tid; slot < cnt;
         slot += gridDim.x * BLK) {
        float4 p = g_pts[slot];
        float cx = p.x, cy = p.y, cz = p.z;
        int ipt = __float_as_int(p.w);

        // h0 accumulator (layer-1 pre-relu), 32 packed regs, fused w/ encode
        u64 h[32];
        #pragma unroll
        for (int j = 0; j < 32; j++) h[j] = 0ull;

        float sc = 16.f;
        #pragma unroll 1
        for (int l = 0; l < 16; l++) {
            float px = cx * sc, py = cy * sc, pz = cz * sc;
            float fx = floorf(px), fy = floorf(py), fz = floorf(pz);
            float tx = px - fx, ty = py - fy, tz = pz - fz;
            unsigned ux = (unsigned)fx, uy = (unsigned)fy, uz = (unsigned)fz;
            unsigned hx0 = ux,      hx1 = ux + 1u;
            unsigned hy0 = uy * P1, hy1 = hy0 + P1;
            unsigned hz0 = uz * P2, hz1 = hz0 + P2;
            unsigned base = (unsigned)l * T_SIZE;
            float wxv[2] = {1.f - tx, tx};
            float wyv[2] = {1.f - ty, ty};
            float wzv[2] = {1.f - tz, tz};

            float a0 = 0.f, a1 = 0.f, a2 = 0.f, a3 = 0.f;
            #pragma unroll
            for (int c = 0; c < 8; c++) {
                unsigned hx = (c & 4) ? hx1 : hx0;
                unsigned hy = (c & 2) ? hy1 : hy0;
                unsigned hz = (c & 1) ? hz1 : hz0;
                unsigned idx = (hx ^ hy ^ hz) & TMASK;
                float4 f = __ldg(tbl + (base + idx));
                float w = wxv[(c >> 2) & 1] * wyv[(c >> 1) & 1] * wzv[c & 1];
                a0 += w * f.x; a1 += w * f.y; a2 += w * f.z; a3 += w * f.w;
            }

            float av[4] = {a0, a1, a2, a3};
            #pragma unroll
            for (int f = 0; f < 4; f++) {
                u64 vv = pk2(av[f], av[f]);
                const ulonglong2* wr = w0v + (l * 4 + f) * 16;
                #pragma unroll
                for (int jj = 0; jj < 16; jj++) {
                    ulonglong2 wp = wr[jj];
                    h[2 * jj + 0] = fma2(vv, wp.x, h[2 * jj + 0]);
                    h[2 * jj + 1] = fma2(vv, wp.y, h[2 * jj + 1]);
                }
            }
            sc *= 2.f;
        }

        // relu(h0) -> smem column (per-thread private), reset acc
        #pragma unroll
        for (int j = 0; j < 32; j++) {
            float2 t = up2(h[j]);
            sact[j * BLK + tid] = pk2(fmaxf(t.x, 0.f), fmaxf(t.y, 0.f));
            h[j] = 0ull;
        }

        // layer 2: h1 = h0r @ w1
        #pragma unroll 1
        for (int ip = 0; ip < 32; ip++) {
            float2 v = up2(sact[ip * BLK + tid]);
            u64 v0 = pk2(v.x, v.x);
            u64 v1 = pk2(v.y, v.y);
            const ulonglong2* r0 = w1v + (2 * ip) * 16;
            const ulonglong2* r1 = r0 + 16;
            #pragma unroll
            for (int jj = 0; jj < 16; jj++) {
                ulonglong2 wa = r0[jj];
                h[2 * jj + 0] = fma2(v0, wa.x, h[2 * jj + 0]);
                h[2 * jj + 1] = fma2(v0, wa.y, h[2 * jj + 1]);
            }
            #pragma unroll
            for (int jj = 0; jj < 16; jj++) {
                ulonglong2 wb = r1[jj];
                h[2 * jj + 0] = fma2(v1, wb.x, h[2 * jj + 0]);
                h[2 * jj + 1] = fma2(v1, wb.y, h[2 * jj + 1]);
            }
        }

        // layer 3: o = relu(h1) @ w2 (64 -> 8), all in registers
        u64 o01 = 0ull, o23 = 0ull, o45 = 0ull, o67 = 0ull;
        u64 q01 = 0ull, q23 = 0ull, q45 = 0ull, q67 = 0ull;
        #pragma unroll
        for (int ip = 0; ip < 32; ip++) {
            float2 v = up2(h[ip]);
            float va = fmaxf(v.x, 0.f), vb = fmaxf(v.y, 0.f);
            u64 pa = pk2(va, va), pb = pk2(vb, vb);
            ulonglong2 wa = w2v[(2 * ip) * 2];       // row 2ip, outs 0-3
            ulonglong2 wb = w2v[(2 * ip) * 2 + 1];   // row 2ip, outs 4-7
            ulonglong2 wc = w2v[(2 * ip + 1) * 2];   // row 2ip+1
            ulonglong2 wd = w2v[(2 * ip + 1) * 2 + 1];
            o01 = fma2(pa, wa.x, o01); o23 = fma2(pa, wa.y, o23);
            o45 = fma2(pa, wb.x, o45); o67 = fma2(pa, wb.y, o67);
            q01 = fma2(pb, wc.x, q01); q23 = fma2(pb, wc.y, q23);
            q45 = fma2(pb, wd.x, q45); q67 = fma2(pb, wd.y, q67);
        }
        float2 f01 = up2(o01), f23 = up2(o23), f45 = up2(o45), f67 = up2(o67);
        float2 g01 = up2(q01), g23 = up2(q23), g45 = up2(q45), g67 = up2(q67);
        float r0 = f01.x + g01.x, r1 = f01.y + g01.y;
        float r2 = f23.x + g23.x, r3 = f23.y + g23.y;
        float r4 = f45.x + g45.x, r5 = f45.y + g45.y;
        float r6 = f67.x + g67.x;

        dxyz[3 * ipt + 0] = r0;
        dxyz[3 * ipt + 1] = r1;
        dxyz[3 * ipt + 2] = r2;
        drot[4 * ipt + 0] = r3;
        drot[4 * ipt + 1] = r4;
        drot[4 * ipt + 2] = r5;
        drot[4 * ipt + 3] = r6;
    }
}

// ---------------- launch ----------------
extern "C" void kernel_launch(void* const* d_in, const int* in_sizes, int n_in,
                              void* d_out, int out_size)
{
    const float* xyz   = (const float*)d_in[0];
    const float* bmin  = (const float*)d_in[1];
    const float* bmax  = (const float*)d_in[2];
    const float* table = (const float*)d_in[3];
    const float* w0    = (const float*)d_in[4];
    const float* w1    = (const float*)d_in[5];
    const float* w2    = (const float*)d_in[6];
    int N = in_sizes[0] / 3;
    float* out = (float*)d_out;

    void* cptr = nullptr;
    cudaGetSymbolAddress(&cptr, g_count);
    cudaMemsetAsync(cptr, 0, sizeof(int), 0);

    int grid1 = (N + 255) / 256;
    k_mask_compact<<<grid1, 256>>>(xyz, bmin, bmax, out, N);

    cudaFuncSetAttribute(k_encode_mlp,
                         cudaFuncAttributeMaxDynamicSharedMemorySize, SMEM_BYTES);
    int grid2 = 296;  // 2 blocks/SM, persistent grid-stride
    k_encode_mlp<<<grid2, BLK, SMEM_BYTES>>>(table, w0, w1, w2, out, N);
}